// round 10
// baseline (speedup 1.0000x reference)
#include <cuda_runtime.h>
#include <math.h>
#include <stdint.h>

#define BB 128
#define NN 512
#define FT 64
#define DD 64
#define TOPK 20
#define M_ROWS (BB*NN)          // 65536
#define NEG_SLOPE 0.2f
#define BN_EPS 1e-5f
#define AP 68                   // mma smem pitch
#define CP 65                   // cos tile pitch (conflict-free)

// ---- scratch (device globals; no allocation allowed) ----
__device__ float g_tsrc[NN];
__device__ float g_tdst[NN];
__device__ int   g_topk[NN*TOPK];
__device__ float g_cos[NN*NN];          // 1 MB
__device__ float g_z[M_ROWS*DD];
__device__ float g_ssrc[M_ROWS];
__device__ float g_sdst[M_ROWS];
__device__ float g_psum[BB*DD];
__device__ float g_psq[BB*DD];
__device__ float g_mu[DD];
__device__ float g_scale[DD];
__device__ unsigned int g_ctr  = 0;
__device__ unsigned int g_ctr2 = 0;
__device__ unsigned int g_done = 0;

__device__ __forceinline__ uint32_t f2tf32(float x) {
    uint32_t r;
    asm("cvt.rna.tf32.f32 %0, %1;" : "=r"(r) : "f"(x));
    return r;
}

#define MMA_TF32(ac, a0,a1,a2,a3, b0,b1) \
    asm volatile("mma.sync.aligned.m16n8k8.row.col.f32.tf32.tf32.f32 " \
        "{%0,%1,%2,%3}, {%4,%5,%6,%7}, {%8,%9}, {%0,%1,%2,%3};" \
        : "+f"((ac)[0]), "+f"((ac)[1]), "+f"((ac)[2]), "+f"((ac)[3]) \
        : "r"(a0), "r"(a1), "r"(a2), "r"(a3), "r"(b0), "r"(b1))

// ============================================================
// kernel 1a: cos-sim matrix, 64x64 tiles, 8x8 grid, 256 thr.
// d-ascending scalar FMA chain == previous passing kernel
// => bit-identical cos values => identical top-k selection.
// bj==0 blocks also compute tsrc/tdst (emb half of scores).
// ============================================================
__global__ void k_cos(const float* __restrict__ emb, const float* __restrict__ attn_w) {
    __shared__ float sa[64*CP];
    __shared__ float sb[64*CP];
    __shared__ float sna[64], snb[64];

    int tid = threadIdx.x;                 // 256
    int i0 = blockIdx.y * 64, j0 = blockIdx.x * 64;

    for (int idx = tid; idx < 4096; idx += 256) {
        int r = idx >> 6, d = idx & 63;
        sa[r*CP + d] = emb[(i0 + r)*64 + d];
        sb[r*CP + d] = emb[(j0 + r)*64 + d];
    }
    __syncthreads();

    if (tid < 64) {                        // norms of A rows (d ascending)
        float s = 0.f;
        #pragma unroll 16
        for (int d = 0; d < 64; d++) { float v = sa[tid*CP + d]; s += v*v; }
        sna[tid] = sqrtf(s);
    } else if (tid < 128) {                // norms of B rows
        int c = tid - 64;
        float s = 0.f;
        #pragma unroll 16
        for (int d = 0; d < 64; d++) { float v = sb[c*CP + d]; s += v*v; }
        snb[c] = sqrtf(s);
    } else if (tid < 192 && blockIdx.x == 0) {   // tsrc/tdst for A rows
        int r = tid - 128;
        float ts = 0.f, td = 0.f;
        #pragma unroll 16
        for (int d = 0; d < 64; d++) {
            float v = sa[r*CP + d];
            ts += v * attn_w[DD + d];
            td += v * attn_w[3*DD + d];
        }
        g_tsrc[i0 + r] = ts;
        g_tdst[i0 + r] = td;
    }
    __syncthreads();

    // thread tile: rows r0..r0+3 (broadcast), cols c0+16j (lane-consecutive)
    int r0 = (tid >> 4) * 4, c0 = tid & 15;
    float acc[4][4] = {};
    #pragma unroll 8
    for (int d = 0; d < 64; d++) {
        float av[4], bv[4];
        #pragma unroll
        for (int i = 0; i < 4; i++) av[i] = sa[(r0+i)*CP + d];
        #pragma unroll
        for (int j = 0; j < 4; j++) bv[j] = sb[(c0 + 16*j)*CP + d];
        #pragma unroll
        for (int i = 0; i < 4; i++)
            #pragma unroll
            for (int j = 0; j < 4; j++)
                acc[i][j] += av[i] * bv[j];
    }
    #pragma unroll
    for (int i = 0; i < 4; i++) {
        float na = sna[r0+i];
        #pragma unroll
        for (int j = 0; j < 4; j++) {
            int c = c0 + 16*j;
            g_cos[(size_t)(i0 + r0 + i)*NN + j0 + c] = acc[i][j] / (na * snb[c]);
        }
    }
}

// ============================================================
// kernel 1b: top-20 selection, warp per row, 32 blocks x 16 warps.
// Same register-selection + tie-break as the passing kernel.
// ============================================================
__global__ void k_sel(int dummy) {
    int tid = threadIdx.x;                 // 512
    int w = tid >> 5, lane = tid & 31;
    int n = blockIdx.x * 16 + w;

    float sl[16];
    #pragma unroll
    for (int j = 0; j < 16; j++) sl[j] = g_cos[(size_t)n*NN + j*32 + lane];  // coalesced

    for (int k = 0; k < TOPK; k++) {
        float bv = sl[0]; int bi = lane;
        #pragma unroll
        for (int j = 1; j < 16; j++) {
            int idx = j*32 + lane;
            if (sl[j] > bv) { bv = sl[j]; bi = idx; }
        }
        #pragma unroll
        for (int o = 16; o > 0; o >>= 1) {
            float ov = __shfl_xor_sync(0xFFFFFFFFu, bv, o);
            int   oi = __shfl_xor_sync(0xFFFFFFFFu, bi, o);
            if (ov > bv || (ov == bv && oi < bi)) { bv = ov; bi = oi; }
        }
        if (lane == 0) g_topk[n*TOPK + k] = bi;
        if ((bi & 31) == lane) {
            int j = bi >> 5;
            #pragma unroll
            for (int jj = 0; jj < 16; jj++) if (jj == j) sl[jj] = -INFINITY;
        }
    }
    (void)dummy;
}

// ============================================================
// kernel 2: z = data @ fc_w^T + fc_b via split-tf32 mma,
// fused with z-part of score dots (independent of topk path).
// ============================================================
__global__ void k_gemm(const float* __restrict__ data,
                       const float* __restrict__ fc_w,
                       const float* __restrict__ fc_b,
                       const float* __restrict__ attn_w) {
    extern __shared__ float gs[];
    float* sAh = gs;
    float* sAl = gs + 128*AP;
    float* sBh = gs + 2*128*AP;
    float* sBl = sBh + 64*AP;

    int tid = threadIdx.x;           // 256
    int rowbase = blockIdx.x * 128;

    {
        const float4* src = reinterpret_cast<const float4*>(data + (size_t)rowbase*64);
        #pragma unroll
        for (int k = 0; k < 8; k++) {
            int i4 = tid + k*256;
            float4 v = src[i4];
            float a[4] = {v.x, v.y, v.z, v.w};
            int base = i4 * 4;
            int r = base >> 6, c = base & 63;
            #pragma unroll
            for (int e = 0; e < 4; e++) {
                uint32_t hb = f2tf32(a[e]);
                float hf = __uint_as_float(hb);
                float lo = a[e] - hf;
                sAh[r*AP + c + e] = hf;
                sAl[r*AP + c + e] = __uint_as_float(f2tf32(lo));
            }
        }
    }
    {
        const float4* src = reinterpret_cast<const float4*>(fc_w);
        #pragma unroll
        for (int k = 0; k < 4; k++) {
            int i4 = tid + k*256;
            float4 v = src[i4];
            float a[4] = {v.x, v.y, v.z, v.w};
            int base = i4 * 4;
            int r = base >> 6, c = base & 63;
            #pragma unroll
            for (int e = 0; e < 4; e++) {
                uint32_t hb = f2tf32(a[e]);
                float hf = __uint_as_float(hb);
                float lo = a[e] - hf;
                sBh[r*AP + c + e] = hf;
                sBl[r*AP + c + e] = __uint_as_float(f2tf32(lo));
            }
        }
    }
    __syncthreads();

    int w = tid >> 5, lane = tid & 31;
    int g = lane >> 2, t = lane & 3;
    int warp_m = w * 16;

    float acc[8][4] = {};
    #pragma unroll
    for (int kk = 0; kk < 8; kk++) {
        int c = kk*8 + t;
        int r0 = warp_m + g;
        uint32_t ah0 = __float_as_uint(sAh[r0*AP + c]);
        uint32_t ah1 = __float_as_uint(sAh[(r0+8)*AP + c]);
        uint32_t ah2 = __float_as_uint(sAh[r0*AP + c + 4]);
        uint32_t ah3 = __float_as_uint(sAh[(r0+8)*AP + c + 4]);
        uint32_t al0 = __float_as_uint(sAl[r0*AP + c]);
        uint32_t al1 = __float_as_uint(sAl[(r0+8)*AP + c]);
        uint32_t al2 = __float_as_uint(sAl[r0*AP + c + 4]);
        uint32_t al3 = __float_as_uint(sAl[(r0+8)*AP + c + 4]);
        #pragma unroll
        for (int j = 0; j < 8; j++) {
            int bn = j*8 + g;
            uint32_t bh0 = __float_as_uint(sBh[bn*AP + c]);
            uint32_t bh1 = __float_as_uint(sBh[bn*AP + c + 4]);
            uint32_t bl0 = __float_as_uint(sBl[bn*AP + c]);
            uint32_t bl1 = __float_as_uint(sBl[bn*AP + c + 4]);
            MMA_TF32(acc[j], ah0, ah1, ah2, ah3, bh0, bh1);   // hi*hi
            MMA_TF32(acc[j], al0, al1, al2, al3, bh0, bh1);   // lo*hi
            MMA_TF32(acc[j], ah0, ah1, ah2, ah3, bl0, bl1);   // hi*lo
        }
    }

    int row0 = rowbase + warp_m + g;
    int row1 = row0 + 8;
    float ds0 = 0.f, dd0 = 0.f, ds1 = 0.f, dd1 = 0.f;
    #pragma unroll
    for (int j = 0; j < 8; j++) {
        int n0 = j*8 + 2*t;
        float b0 = __ldg(&fc_b[n0]), b1 = __ldg(&fc_b[n0+1]);
        float z00 = acc[j][0] + b0, z01 = acc[j][1] + b1;
        float z10 = acc[j][2] + b0, z11 = acc[j][3] + b1;
        float2 v0; v0.x = z00; v0.y = z01;
        float2 v1; v1.x = z10; v1.y = z11;
        *reinterpret_cast<float2*>(&g_z[(size_t)row0*64 + n0]) = v0;
        *reinterpret_cast<float2*>(&g_z[(size_t)row1*64 + n0]) = v1;
        float as0 = __ldg(&attn_w[n0]),     as1 = __ldg(&attn_w[n0+1]);
        float ad0 = __ldg(&attn_w[128+n0]), ad1 = __ldg(&attn_w[128+n0+1]);
        ds0 += z00*as0 + z01*as1;  dd0 += z00*ad0 + z01*ad1;
        ds1 += z10*as0 + z11*as1;  dd1 += z10*ad0 + z11*ad1;
    }
    #pragma unroll
    for (int o = 2; o > 0; o >>= 1) {
        ds0 += __shfl_down_sync(0xFFFFFFFFu, ds0, o, 4);
        dd0 += __shfl_down_sync(0xFFFFFFFFu, dd0, o, 4);
        ds1 += __shfl_down_sync(0xFFFFFFFFu, ds1, o, 4);
        dd1 += __shfl_down_sync(0xFFFFFFFFu, dd1, o, 4);
    }
    if (t == 0) {
        g_ssrc[row0] = ds0;   // z-part only; tsrc/tdst folded in k_aggr
        g_sdst[row0] = dd0;
        g_ssrc[row1] = ds1;
        g_sdst[row1] = dd1;
    }
}

// ============================================================
// kernel 3: per-batch block (128 blocks = 1 wave, all co-resident).
// softmax + aggregate + BN partials; software grid-sync; then
// BN-normalize + relu + out-projection straight from registers.
// ============================================================
__global__ void k_aggr(const float* __restrict__ emb, const float* __restrict__ attn_b,
                       const float* __restrict__ bn_gamma, const float* __restrict__ bn_beta,
                       const float* __restrict__ out_w, const float* __restrict__ out_b,
                       float* __restrict__ out) {
    extern __shared__ float smem[];
    float* zs   = smem;                       // 32768 floats
    float* aval = smem + NN*DD;               // 10240 floats
    int*   aidx = (int*)(smem + NN*DD + NN*TOPK);
    __shared__ float wsum[16][64];
    __shared__ float wsq[16][64];
    __shared__ float s_ssrc[NN];              // ssrc_z + tsrc, this batch
    __shared__ unsigned int s_last;

    int tid = threadIdx.x;                    // 512 threads
    int b = blockIdx.x;
    int lane = tid & 31, w = tid >> 5;

    const float4* zsrc = reinterpret_cast<const float4*>(&g_z[(size_t)b * NN * DD]);
    float4* zdst = reinterpret_cast<float4*>(zs);
    #pragma unroll
    for (int i = 0; i < 16; i++) zdst[tid + i*512] = zsrc[tid + i*512];

    s_ssrc[tid] = g_ssrc[b*NN + tid] + g_tsrc[tid];
    __syncthreads();

    {
        int n = tid;
        float sd = g_sdst[b*NN + n] + g_tdst[n] + __ldg(attn_b);
        float e[TOPK]; int sr[TOPK];
        float mx = -INFINITY;
        #pragma unroll
        for (int t = 0; t < TOPK; t++) {
            int i = n + t*NN;
            int s = g_topk[(i/TOPK)*TOPK + (i % TOPK)];   // reference's edge wiring
            sr[t] = s;
            float x = s_ssrc[s] + sd;
            x = x > 0.f ? x : NEG_SLOPE * x;
            e[t] = x;
            mx = fmaxf(mx, x);
        }
        float den = 0.f;
        #pragma unroll
        for (int t = 0; t < TOPK; t++) { float p = expf(e[t] - mx); e[t] = p; den += p; }
        float inv = 1.0f / den;
        #pragma unroll
        for (int t = 0; t < TOPK; t++) { aval[n*TOPK + t] = e[t]*inv; aidx[n*TOPK + t] = sr[t]; }
    }
    __syncthreads();

    float rr0[32], rr1[32];
    float ps0 = 0.f, pq0 = 0.f, ps1 = 0.f, pq1 = 0.f;
    int nbase = w * 32;
    #pragma unroll
    for (int rr = 0; rr < 32; rr++) {
        int n = nbase + rr;
        float h0 = 0.f, h1 = 0.f;
        #pragma unroll
        for (int t = 0; t < TOPK; t++) {
            float a = aval[n*TOPK + t];
            int   s = aidx[n*TOPK + t];
            h0 = fmaf(a, zs[s*64 + lane], h0);
            h1 = fmaf(a, zs[s*64 + 32 + lane], h1);
        }
        float e0 = emb[n*64 + lane];
        float e1 = emb[n*64 + 32 + lane];
        float r0 = h0 * e0, r1 = h1 * e1;
        rr0[rr] = r0; rr1[rr] = r1;
        ps0 += r0; pq0 += r0*r0;
        ps1 += r1; pq1 += r1*r1;
    }
    wsum[w][lane] = ps0; wsum[w][lane+32] = ps1;
    wsq [w][lane] = pq0; wsq [w][lane+32] = pq1;
    __syncthreads();
    if (tid < 64) {
        float S = 0.f, Q = 0.f;
        #pragma unroll
        for (int ww = 0; ww < 16; ww++) { S += wsum[ww][tid]; Q += wsq[ww][tid]; }
        g_psum[b*64 + tid] = S;
        g_psq [b*64 + tid] = Q;
    }
    __threadfence();
    __syncthreads();
    if (tid == 0) s_last = (atomicAdd(&g_ctr, 1u) == BB - 1u) ? 1u : 0u;
    __syncthreads();

    if (s_last) {
        __threadfence();
        int d = tid & 63, grp = tid >> 6;
        float s = 0.f, q = 0.f;
        #pragma unroll
        for (int jj = 0; jj < 16; jj++) {
            int j = grp*16 + jj;
            s += g_psum[j*64 + d];
            q += g_psq [j*64 + d];
        }
        __syncthreads();
        wsum[grp][d] = s; wsq[grp][d] = q;
        __syncthreads();
        if (tid < 64) {
            float S = 0.f, Q = 0.f;
            #pragma unroll
            for (int gg = 0; gg < 8; gg++) { S += wsum[gg][tid]; Q += wsq[gg][tid]; }
            float mu  = S / (float)M_ROWS;
            float var = Q / (float)M_ROWS - mu*mu;   // biased, matches jnp.var
            g_mu[tid]    = mu;
            g_scale[tid] = bn_gamma[tid] / sqrtf(var + BN_EPS);
        }
        __threadfence();
        __syncthreads();
        if (tid == 0) atomicExch(&g_done, 1u);
    }

    if (tid == 0) {
        while (atomicAdd(&g_done, 0u) == 0u) { }
    }
    __syncthreads();
    __threadfence();

    {
        float mu0 = g_mu[lane],       mu1 = g_mu[lane+32];
        float sc0 = g_scale[lane],    sc1 = g_scale[lane+32];
        float bt0 = bn_beta[lane],    bt1 = bn_beta[lane+32];
        float ow0 = out_w[lane],      ow1 = out_w[lane+32];
        float ob  = __ldg(out_b);
        #pragma unroll
        for (int rr = 0; rr < 32; rr++) {
            float v0 = (rr0[rr] - mu0) * sc0 + bt0;
            float v1 = (rr1[rr] - mu1) * sc1 + bt1;
            v0 = v0 > 0.f ? v0 : 0.f;
            v1 = v1 > 0.f ? v1 : 0.f;
            float a = v0*ow0 + v1*ow1;
            #pragma unroll
            for (int o = 16; o > 0; o >>= 1) a += __shfl_down_sync(0xFFFFFFFFu, a, o);
            if (lane == 0) out[b*NN + nbase + rr] = a + ob;
        }
    }

    __syncthreads();
    if (tid == 0) {
        if (atomicAdd(&g_ctr2, 1u) == BB - 1u) {
            g_ctr = 0; g_ctr2 = 0; g_done = 0;
            __threadfence();
        }
    }
}

extern "C" void kernel_launch(void* const* d_in, const int* in_sizes, int n_in,
                              void* d_out, int out_size) {
    const float* data     = (const float*)d_in[0];
    const float* emb      = (const float*)d_in[1];
    const float* fc_w     = (const float*)d_in[2];
    const float* fc_b     = (const float*)d_in[3];
    const float* attn_w   = (const float*)d_in[4];
    const float* attn_b   = (const float*)d_in[5];
    const float* bn_gamma = (const float*)d_in[6];
    const float* bn_beta  = (const float*)d_in[7];
    const float* out_w    = (const float*)d_in[8];
    const float* out_b    = (const float*)d_in[9];
    float* out = (float*)d_out;

    const int AGG_SMEM  = (NN*DD + 2*NN*TOPK) * 4;                   // 212992 bytes
    const int GEMM_SMEM = (2*128*AP + 2*64*AP) * 4;                  // 104448 bytes

    static cudaStream_t s2 = nullptr;
    static cudaEvent_t evFork = nullptr, evJoin = nullptr;
    if (!s2) {
        cudaFuncSetAttribute(k_aggr, cudaFuncAttributeMaxDynamicSharedMemorySize, AGG_SMEM);
        cudaFuncSetAttribute(k_gemm, cudaFuncAttributeMaxDynamicSharedMemorySize, GEMM_SMEM);
        cudaStreamCreateWithFlags(&s2, cudaStreamNonBlocking);
        cudaEventCreateWithFlags(&evFork, cudaEventDisableTiming);
        cudaEventCreateWithFlags(&evJoin, cudaEventDisableTiming);
    }

    // fork: cos+sel on s2 run concurrently with k_gemm on the main stream
    cudaEventRecord(evFork, 0);
    cudaStreamWaitEvent(s2, evFork, 0);
    k_cos <<<dim3(8,8), 256, 0, s2>>>(emb, attn_w);
    k_sel <<<32, 512, 0, s2>>>(0);
    cudaEventRecord(evJoin, s2);

    k_gemm <<<M_ROWS/128, 256, GEMM_SMEM>>>(data, fc_w, fc_b, attn_w);

    // join: k_aggr needs g_topk/g_tsrc/g_tdst (s2) and g_z/g_ssrc/g_sdst (gemm)
    cudaStreamWaitEvent(0, evJoin, 0);
    k_aggr <<<BB, 512, AGG_SMEM>>>(emb, attn_b, bn_gamma, bn_beta, out_w, out_b, out);
}

// round 11
// speedup vs baseline: 1.0057x; 1.0057x over previous
#include <cuda_runtime.h>
#include <math.h>
#include <stdint.h>

#define BB 128
#define NN 512
#define FT 64
#define DD 64
#define TOPK 20
#define M_ROWS (BB*NN)          // 65536
#define NEG_SLOPE 0.2f
#define BN_EPS 1e-5f
#define AP 68                   // mma smem pitch
#define CP 65                   // cos tile pitch (conflict-free)

// ---- scratch (device globals; no allocation allowed) ----
__device__ float g_tsrc[NN];
__device__ float g_tdst[NN];
__device__ int   g_topk[NN*TOPK];
__device__ float g_cos[NN*NN];          // 1 MB
__device__ float g_z[M_ROWS*DD];
__device__ float g_rst[M_ROWS*DD];      // 16 MB staging (coalesced)
__device__ float g_ssrc[M_ROWS];
__device__ float g_sdst[M_ROWS];
__device__ float g_psum[BB*DD];
__device__ float g_psq[BB*DD];
__device__ float g_mu[DD];
__device__ float g_scale[DD];
__device__ unsigned int g_ctr  = 0;
__device__ unsigned int g_ctr2 = 0;
__device__ unsigned int g_done = 0;

__device__ __forceinline__ uint32_t f2tf32(float x) {
    uint32_t r;
    asm("cvt.rna.tf32.f32 %0, %1;" : "=r"(r) : "f"(x));
    return r;
}

#define MMA_TF32(ac, a0,a1,a2,a3, b0,b1) \
    asm volatile("mma.sync.aligned.m16n8k8.row.col.f32.tf32.tf32.f32 " \
        "{%0,%1,%2,%3}, {%4,%5,%6,%7}, {%8,%9}, {%0,%1,%2,%3};" \
        : "+f"((ac)[0]), "+f"((ac)[1]), "+f"((ac)[2]), "+f"((ac)[3]) \
        : "r"(a0), "r"(a1), "r"(a2), "r"(a3), "r"(b0), "r"(b1))

// ============================================================
// kernel 1a: cos-sim matrix, 64x64 tiles, 8x8 grid, 256 thr.
// d-ascending scalar FMA chain => bit-identical cos values.
// bj==0 blocks also compute tsrc/tdst (emb half of scores).
// ============================================================
__global__ void k_cos(const float* __restrict__ emb, const float* __restrict__ attn_w) {
    __shared__ float sa[64*CP];
    __shared__ float sb[64*CP];
    __shared__ float sna[64], snb[64];

    int tid = threadIdx.x;                 // 256
    int i0 = blockIdx.y * 64, j0 = blockIdx.x * 64;

    for (int idx = tid; idx < 4096; idx += 256) {
        int r = idx >> 6, d = idx & 63;
        sa[r*CP + d] = emb[(i0 + r)*64 + d];
        sb[r*CP + d] = emb[(j0 + r)*64 + d];
    }
    __syncthreads();

    if (tid < 64) {
        float s = 0.f;
        #pragma unroll 16
        for (int d = 0; d < 64; d++) { float v = sa[tid*CP + d]; s += v*v; }
        sna[tid] = sqrtf(s);
    } else if (tid < 128) {
        int c = tid - 64;
        float s = 0.f;
        #pragma unroll 16
        for (int d = 0; d < 64; d++) { float v = sb[c*CP + d]; s += v*v; }
        snb[c] = sqrtf(s);
    } else if (tid < 192 && blockIdx.x == 0) {
        int r = tid - 128;
        float ts = 0.f, td = 0.f;
        #pragma unroll 16
        for (int d = 0; d < 64; d++) {
            float v = sa[r*CP + d];
            ts += v * attn_w[DD + d];
            td += v * attn_w[3*DD + d];
        }
        g_tsrc[i0 + r] = ts;
        g_tdst[i0 + r] = td;
    }
    __syncthreads();

    int r0 = (tid >> 4) * 4, c0 = tid & 15;
    float acc[4][4] = {};
    #pragma unroll 8
    for (int d = 0; d < 64; d++) {
        float av[4], bv[4];
        #pragma unroll
        for (int i = 0; i < 4; i++) av[i] = sa[(r0+i)*CP + d];
        #pragma unroll
        for (int j = 0; j < 4; j++) bv[j] = sb[(c0 + 16*j)*CP + d];
        #pragma unroll
        for (int i = 0; i < 4; i++)
            #pragma unroll
            for (int j = 0; j < 4; j++)
                acc[i][j] += av[i] * bv[j];
    }
    #pragma unroll
    for (int i = 0; i < 4; i++) {
        float na = sna[r0+i];
        #pragma unroll
        for (int j = 0; j < 4; j++) {
            int c = c0 + 16*j;
            g_cos[(size_t)(i0 + r0 + i)*NN + j0 + c] = acc[i][j] / (na * snb[c]);
        }
    }
}

// ============================================================
// kernel 1b: top-20 selection, warp per row, 32 blocks x 16 warps.
// ============================================================
__global__ void k_sel(int dummy) {
    int tid = threadIdx.x;                 // 512
    int w = tid >> 5, lane = tid & 31;
    int n = blockIdx.x * 16 + w;

    float sl[16];
    #pragma unroll
    for (int j = 0; j < 16; j++) sl[j] = g_cos[(size_t)n*NN + j*32 + lane];

    for (int k = 0; k < TOPK; k++) {
        float bv = sl[0]; int bi = lane;
        #pragma unroll
        for (int j = 1; j < 16; j++) {
            int idx = j*32 + lane;
            if (sl[j] > bv) { bv = sl[j]; bi = idx; }
        }
        #pragma unroll
        for (int o = 16; o > 0; o >>= 1) {
            float ov = __shfl_xor_sync(0xFFFFFFFFu, bv, o);
            int   oi = __shfl_xor_sync(0xFFFFFFFFu, bi, o);
            if (ov > bv || (ov == bv && oi < bi)) { bv = ov; bi = oi; }
        }
        if (lane == 0) g_topk[n*TOPK + k] = bi;
        if ((bi & 31) == lane) {
            int j = bi >> 5;
            #pragma unroll
            for (int jj = 0; jj < 16; jj++) if (jj == j) sl[jj] = -INFINITY;
        }
    }
    (void)dummy;
}

// ============================================================
// kernel 2: z = data @ fc_w^T + fc_b via split-tf32 mma,
// fused with z-part of score dots.
// ============================================================
__global__ void k_gemm(const float* __restrict__ data,
                       const float* __restrict__ fc_w,
                       const float* __restrict__ fc_b,
                       const float* __restrict__ attn_w) {
    extern __shared__ float gs[];
    float* sAh = gs;
    float* sAl = gs + 128*AP;
    float* sBh = gs + 2*128*AP;
    float* sBl = sBh + 64*AP;

    int tid = threadIdx.x;           // 256
    int rowbase = blockIdx.x * 128;

    {
        const float4* src = reinterpret_cast<const float4*>(data + (size_t)rowbase*64);
        #pragma unroll
        for (int k = 0; k < 8; k++) {
            int i4 = tid + k*256;
            float4 v = src[i4];
            float a[4] = {v.x, v.y, v.z, v.w};
            int base = i4 * 4;
            int r = base >> 6, c = base & 63;
            #pragma unroll
            for (int e = 0; e < 4; e++) {
                uint32_t hb = f2tf32(a[e]);
                float hf = __uint_as_float(hb);
                float lo = a[e] - hf;
                sAh[r*AP + c + e] = hf;
                sAl[r*AP + c + e] = __uint_as_float(f2tf32(lo));
            }
        }
    }
    {
        const float4* src = reinterpret_cast<const float4*>(fc_w);
        #pragma unroll
        for (int k = 0; k < 4; k++) {
            int i4 = tid + k*256;
            float4 v = src[i4];
            float a[4] = {v.x, v.y, v.z, v.w};
            int base = i4 * 4;
            int r = base >> 6, c = base & 63;
            #pragma unroll
            for (int e = 0; e < 4; e++) {
                uint32_t hb = f2tf32(a[e]);
                float hf = __uint_as_float(hb);
                float lo = a[e] - hf;
                sBh[r*AP + c + e] = hf;
                sBl[r*AP + c + e] = __uint_as_float(f2tf32(lo));
            }
        }
    }
    __syncthreads();

    int w = tid >> 5, lane = tid & 31;
    int g = lane >> 2, t = lane & 3;
    int warp_m = w * 16;

    float acc[8][4] = {};
    #pragma unroll
    for (int kk = 0; kk < 8; kk++) {
        int c = kk*8 + t;
        int r0 = warp_m + g;
        uint32_t ah0 = __float_as_uint(sAh[r0*AP + c]);
        uint32_t ah1 = __float_as_uint(sAh[(r0+8)*AP + c]);
        uint32_t ah2 = __float_as_uint(sAh[r0*AP + c + 4]);
        uint32_t ah3 = __float_as_uint(sAh[(r0+8)*AP + c + 4]);
        uint32_t al0 = __float_as_uint(sAl[r0*AP + c]);
        uint32_t al1 = __float_as_uint(sAl[(r0+8)*AP + c]);
        uint32_t al2 = __float_as_uint(sAl[r0*AP + c + 4]);
        uint32_t al3 = __float_as_uint(sAl[(r0+8)*AP + c + 4]);
        #pragma unroll
        for (int j = 0; j < 8; j++) {
            int bn = j*8 + g;
            uint32_t bh0 = __float_as_uint(sBh[bn*AP + c]);
            uint32_t bh1 = __float_as_uint(sBh[bn*AP + c + 4]);
            uint32_t bl0 = __float_as_uint(sBl[bn*AP + c]);
            uint32_t bl1 = __float_as_uint(sBl[bn*AP + c + 4]);
            MMA_TF32(acc[j], ah0, ah1, ah2, ah3, bh0, bh1);   // hi*hi
            MMA_TF32(acc[j], al0, al1, al2, al3, bh0, bh1);   // lo*hi
            MMA_TF32(acc[j], ah0, ah1, ah2, ah3, bl0, bl1);   // hi*lo
        }
    }

    int row0 = rowbase + warp_m + g;
    int row1 = row0 + 8;
    float ds0 = 0.f, dd0 = 0.f, ds1 = 0.f, dd1 = 0.f;
    #pragma unroll
    for (int j = 0; j < 8; j++) {
        int n0 = j*8 + 2*t;
        float b0 = __ldg(&fc_b[n0]), b1 = __ldg(&fc_b[n0+1]);
        float z00 = acc[j][0] + b0, z01 = acc[j][1] + b1;
        float z10 = acc[j][2] + b0, z11 = acc[j][3] + b1;
        float2 v0; v0.x = z00; v0.y = z01;
        float2 v1; v1.x = z10; v1.y = z11;
        *reinterpret_cast<float2*>(&g_z[(size_t)row0*64 + n0]) = v0;
        *reinterpret_cast<float2*>(&g_z[(size_t)row1*64 + n0]) = v1;
        float as0 = __ldg(&attn_w[n0]),     as1 = __ldg(&attn_w[n0+1]);
        float ad0 = __ldg(&attn_w[128+n0]), ad1 = __ldg(&attn_w[128+n0+1]);
        ds0 += z00*as0 + z01*as1;  dd0 += z00*ad0 + z01*ad1;
        ds1 += z10*as0 + z11*as1;  dd1 += z10*ad0 + z11*ad1;
    }
    #pragma unroll
    for (int o = 2; o > 0; o >>= 1) {
        ds0 += __shfl_down_sync(0xFFFFFFFFu, ds0, o, 4);
        dd0 += __shfl_down_sync(0xFFFFFFFFu, dd0, o, 4);
        ds1 += __shfl_down_sync(0xFFFFFFFFu, ds1, o, 4);
        dd1 += __shfl_down_sync(0xFFFFFFFFu, dd1, o, 4);
    }
    if (t == 0) {
        g_ssrc[row0] = ds0;   // z-part only; tsrc/tdst folded in k_aggr
        g_sdst[row0] = dd0;
        g_ssrc[row1] = ds1;
        g_sdst[row1] = dd1;
    }
}

// ============================================================
// kernel 3: per-batch block, 1024 threads (32 warps, 16 rows/warp).
// softmax + aggregate (rst -> g_rst) + BN partials; software
// grid-sync; BN-normalize + relu + out-projection.
// dyn smem: zs[512*64] | apack[512*20] float2   (213 KB)
// apack region reused for warp partial sums after aggregation.
// ============================================================
__global__ void __launch_bounds__(1024, 1)
k_aggr(const float* __restrict__ emb, const float* __restrict__ attn_b,
       const float* __restrict__ bn_gamma, const float* __restrict__ bn_beta,
       const float* __restrict__ out_w, const float* __restrict__ out_b,
       float* __restrict__ out) {
    extern __shared__ float smem[];
    float*  zs    = smem;                             // 32768 floats
    float2* apack = (float2*)(smem + NN*DD);          // 10240 float2 (80 KB)
    // post-aggregation reuse of the apack region:
    float* wsum = smem + NN*DD;                       // [32][64]
    float* wsq  = smem + NN*DD + 32*64;               // [32][64]
    __shared__ float s_ssrc[NN];
    __shared__ unsigned int s_last;

    int tid = threadIdx.x;                            // 1024 threads
    int b = blockIdx.x;
    int lane = tid & 31, w = tid >> 5;                // w: 0..31

    // load z[b] slice (128KB) via float4: 8 per thread
    const float4* zsrc = reinterpret_cast<const float4*>(&g_z[(size_t)b * NN * DD]);
    float4* zdst = reinterpret_cast<float4*>(zs);
    #pragma unroll
    for (int i = 0; i < 8; i++) zdst[tid + i*1024] = zsrc[tid + i*1024];

    if (tid < NN) s_ssrc[tid] = g_ssrc[b*NN + tid] + g_tsrc[tid];
    __syncthreads();

    // alphas: threads 0..511, one dst row each
    if (tid < NN) {
        int n = tid;
        float sd = g_sdst[b*NN + n] + g_tdst[n] + __ldg(attn_b);
        float e[TOPK]; int sr[TOPK];
        float mx = -INFINITY;
        #pragma unroll
        for (int t = 0; t < TOPK; t++) {
            int i = n + t*NN;
            int s = g_topk[(i/TOPK)*TOPK + (i % TOPK)];   // reference's edge wiring
            sr[t] = s;
            float x = s_ssrc[s] + sd;
            x = x > 0.f ? x : NEG_SLOPE * x;              // leaky relu
            e[t] = x;
            mx = fmaxf(mx, x);
        }
        float den = 0.f;
        #pragma unroll
        for (int t = 0; t < TOPK; t++) { float p = expf(e[t] - mx); e[t] = p; den += p; }
        float inv = 1.0f / den;
        #pragma unroll
        for (int t = 0; t < TOPK; t++) {
            float2 pk; pk.x = e[t]*inv; pk.y = __int_as_float(sr[t]);
            apack[n*TOPK + t] = pk;
        }
    }
    __syncthreads();

    // aggregate: warp w -> rows n = w*16 .. w*16+15; lane = d (and d+32)
    float ps0 = 0.f, pq0 = 0.f, ps1 = 0.f, pq1 = 0.f;
    int nbase = w * 16;
    #pragma unroll
    for (int rr = 0; rr < 16; rr++) {
        int n = nbase + rr;
        float h0 = 0.f, h1 = 0.f;
        #pragma unroll
        for (int t = 0; t < TOPK; t++) {
            float2 pk = apack[n*TOPK + t];    // one LDS.64 broadcast
            float a = pk.x;
            int   s = __float_as_int(pk.y);
            h0 = fmaf(a, zs[s*64 + lane], h0);
            h1 = fmaf(a, zs[s*64 + 32 + lane], h1);
        }
        float e0 = emb[n*64 + lane];
        float e1 = emb[n*64 + 32 + lane];
        float r0 = h0 * e0, r1 = h1 * e1;
        size_t row = (size_t)b*NN + n;
        g_rst[row*64 + lane]      = r0;       // coalesced STG
        g_rst[row*64 + 32 + lane] = r1;
        ps0 += r0; pq0 += r0*r0;
        ps1 += r1; pq1 += r1*r1;
    }
    __syncthreads();                          // apack reads done -> reuse region
    wsum[w*64 + lane]      = ps0; wsum[w*64 + lane+32] = ps1;
    wsq [w*64 + lane]      = pq0; wsq [w*64 + lane+32] = pq1;
    __syncthreads();
    if (tid < 64) {
        float S = 0.f, Q = 0.f;
        #pragma unroll
        for (int ww = 0; ww < 32; ww++) { S += wsum[ww*64 + tid]; Q += wsq[ww*64 + tid]; }
        g_psum[b*64 + tid] = S;
        g_psq [b*64 + tid] = Q;
    }
    __threadfence();
    __syncthreads();
    if (tid == 0) s_last = (atomicAdd(&g_ctr, 1u) == BB - 1u) ? 1u : 0u;
    __syncthreads();

    if (s_last) {
        __threadfence();                      // acquire: all blocks' psum visible
        int d = tid & 63, grp = tid >> 6;     // 16 groups x 64 d, 8 batches each
        float s = 0.f, q = 0.f;
        #pragma unroll
        for (int jj = 0; jj < 8; jj++) {
            int j = grp*8 + jj;
            s += g_psum[j*64 + d];
            q += g_psq [j*64 + d];
        }
        __syncthreads();
        wsum[grp*64 + d] = s; wsq[grp*64 + d] = q;
        __syncthreads();
        if (tid < 64) {
            float S = 0.f, Q = 0.f;
            #pragma unroll
            for (int gg = 0; gg < 16; gg++) { S += wsum[gg*64 + tid]; Q += wsq[gg*64 + tid]; }
            float mu  = S / (float)M_ROWS;
            float var = Q / (float)M_ROWS - mu*mu;   // biased, matches jnp.var
            g_mu[tid]    = mu;
            g_scale[tid] = bn_gamma[tid] / sqrtf(var + BN_EPS);
        }
        __threadfence();
        __syncthreads();
        if (tid == 0) atomicExch(&g_done, 1u);
    }

    // grid-wide wait: 128 blocks, 1/SM, all co-resident
    if (tid == 0) {
        while (atomicAdd(&g_done, 0u) == 0u) { }
    }
    __syncthreads();
    __threadfence();

    // BN-normalize + relu + out projection (read rst back, coalesced)
    {
        float mu0 = g_mu[lane],       mu1 = g_mu[lane+32];
        float sc0 = g_scale[lane],    sc1 = g_scale[lane+32];
        float bt0 = bn_beta[lane],    bt1 = bn_beta[lane+32];
        float ow0 = out_w[lane],      ow1 = out_w[lane+32];
        float ob  = __ldg(out_b);
        #pragma unroll
        for (int rr = 0; rr < 16; rr++) {
            size_t row = (size_t)b*NN + nbase + rr;
            float v0 = (g_rst[row*64 + lane]      - mu0) * sc0 + bt0;
            float v1 = (g_rst[row*64 + 32 + lane] - mu1) * sc1 + bt1;
            v0 = v0 > 0.f ? v0 : 0.f;
            v1 = v1 > 0.f ? v1 : 0.f;
            float a = v0*ow0 + v1*ow1;
            #pragma unroll
            for (int o = 16; o > 0; o >>= 1) a += __shfl_down_sync(0xFFFFFFFFu, a, o);
            if (lane == 0) out[b*NN + nbase + rr] = a + ob;
        }
    }

    // reset counters for next graph replay (last block to depart)
    __syncthreads();
    if (tid == 0) {
        if (atomicAdd(&g_ctr2, 1u) == BB - 1u) {
            g_ctr = 0; g_ctr2 = 0; g_done = 0;
            __threadfence();
        }
    }
}

extern "C" void kernel_launch(void* const* d_in, const int* in_sizes, int n_in,
                              void* d_out, int out_size) {
    const float* data     = (const float*)d_in[0];
    const float* emb      = (const float*)d_in[1];
    const float* fc_w     = (const float*)d_in[2];
    const float* fc_b     = (const float*)d_in[3];
    const float* attn_w   = (const float*)d_in[4];
    const float* attn_b   = (const float*)d_in[5];
    const float* bn_gamma = (const float*)d_in[6];
    const float* bn_beta  = (const float*)d_in[7];
    const float* out_w    = (const float*)d_in[8];
    const float* out_b    = (const float*)d_in[9];
    float* out = (float*)d_out;

    const int AGG_SMEM  = (NN*DD + 2*NN*TOPK) * 4;                   // 212992 bytes
    const int GEMM_SMEM = (2*128*AP + 2*64*AP) * 4;                  // 104448 bytes

    static cudaStream_t s2 = nullptr;
    static cudaEvent_t evFork = nullptr, evJoin = nullptr;
    if (!s2) {
        cudaFuncSetAttribute(k_aggr, cudaFuncAttributeMaxDynamicSharedMemorySize, AGG_SMEM);
        cudaFuncSetAttribute(k_gemm, cudaFuncAttributeMaxDynamicSharedMemorySize, GEMM_SMEM);
        cudaStreamCreateWithFlags(&s2, cudaStreamNonBlocking);
        cudaEventCreateWithFlags(&evFork, cudaEventDisableTiming);
        cudaEventCreateWithFlags(&evJoin, cudaEventDisableTiming);
    }

    // fork: cos+sel on s2 run concurrently with k_gemm on the main stream
    cudaEventRecord(evFork, 0);
    cudaStreamWaitEvent(s2, evFork, 0);
    k_cos <<<dim3(8,8), 256, 0, s2>>>(emb, attn_w);
    k_sel <<<32, 512, 0, s2>>>(0);
    cudaEventRecord(evJoin, s2);

    k_gemm <<<M_ROWS/128, 256, GEMM_SMEM>>>(data, fc_w, fc_b, attn_w);

    // join: k_aggr needs g_topk/g_tsrc/g_tdst (s2) and g_z/g_ssrc/g_sdst (gemm)
    cudaStreamWaitEvent(0, evJoin, 0);
    k_aggr <<<BB, 1024, AGG_SMEM>>>(emb, attn_b, bn_gamma, bn_beta, out_w, out_b, out);
}

// round 12
// speedup vs baseline: 1.0085x; 1.0028x over previous
#include <cuda_runtime.h>
#include <math.h>
#include <stdint.h>

#define BB 128
#define NN 512
#define FT 64
#define DD 64
#define TOPK 20
#define M_ROWS (BB*NN)          // 65536
#define NEG_SLOPE 0.2f
#define BN_EPS 1e-5f
#define CP 65                   // cos tile pitch (conflict-free)
#define BP 68                   // B smem pitch (bank = 4g+t, conflict-free)

// ---- scratch (device globals; no allocation allowed) ----
__device__ float g_tsrc[NN];
__device__ float g_tdst[NN];
__device__ int   g_topk[NN*TOPK];
__device__ float g_cos[NN*NN];          // 1 MB
__device__ float g_rst[M_ROWS*DD];      // 16 MB staging (coalesced)
__device__ float g_psum[BB*DD];
__device__ float g_psq[BB*DD];
__device__ float g_mu[DD];
__device__ float g_scale[DD];
__device__ unsigned int g_ctr  = 0;
__device__ unsigned int g_ctr2 = 0;
__device__ unsigned int g_done = 0;

__device__ __forceinline__ uint32_t f2tf32(float x) {
    uint32_t r;
    asm("cvt.rna.tf32.f32 %0, %1;" : "=r"(r) : "f"(x));
    return r;
}

#define MMA_TF32(ac, a0,a1,a2,a3, b0,b1) \
    asm volatile("mma.sync.aligned.m16n8k8.row.col.f32.tf32.tf32.f32 " \
        "{%0,%1,%2,%3}, {%4,%5,%6,%7}, {%8,%9}, {%0,%1,%2,%3};" \
        : "+f"((ac)[0]), "+f"((ac)[1]), "+f"((ac)[2]), "+f"((ac)[3]) \
        : "r"(a0), "r"(a1), "r"(a2), "r"(a3), "r"(b0), "r"(b1))

// ============================================================
// kernel 1a: cos-sim matrix, 64x64 tiles, 8x8 grid, 256 thr.
// d-ascending scalar FMA chain => bit-identical cos values.
// bj==0 blocks also compute tsrc/tdst (emb half of scores).
// ============================================================
__global__ void k_cos(const float* __restrict__ emb, const float* __restrict__ attn_w) {
    __shared__ float sa[64*CP];
    __shared__ float sb[64*CP];
    __shared__ float sna[64], snb[64];

    int tid = threadIdx.x;                 // 256
    int i0 = blockIdx.y * 64, j0 = blockIdx.x * 64;

    for (int idx = tid; idx < 4096; idx += 256) {
        int r = idx >> 6, d = idx & 63;
        sa[r*CP + d] = emb[(i0 + r)*64 + d];
        sb[r*CP + d] = emb[(j0 + r)*64 + d];
    }
    __syncthreads();

    if (tid < 64) {
        float s = 0.f;
        #pragma unroll 16
        for (int d = 0; d < 64; d++) { float v = sa[tid*CP + d]; s += v*v; }
        sna[tid] = sqrtf(s);
    } else if (tid < 128) {
        int c = tid - 64;
        float s = 0.f;
        #pragma unroll 16
        for (int d = 0; d < 64; d++) { float v = sb[c*CP + d]; s += v*v; }
        snb[c] = sqrtf(s);
    } else if (tid < 192 && blockIdx.x == 0) {
        int r = tid - 128;
        float ts = 0.f, td = 0.f;
        #pragma unroll 16
        for (int d = 0; d < 64; d++) {
            float v = sa[r*CP + d];
            ts += v * attn_w[DD + d];
            td += v * attn_w[3*DD + d];
        }
        g_tsrc[i0 + r] = ts;
        g_tdst[i0 + r] = td;
    }
    __syncthreads();

    int r0 = (tid >> 4) * 4, c0 = tid & 15;
    float acc[4][4] = {};
    #pragma unroll 8
    for (int d = 0; d < 64; d++) {
        float av[4], bv[4];
        #pragma unroll
        for (int i = 0; i < 4; i++) av[i] = sa[(r0+i)*CP + d];
        #pragma unroll
        for (int j = 0; j < 4; j++) bv[j] = sb[(c0 + 16*j)*CP + d];
        #pragma unroll
        for (int i = 0; i < 4; i++)
            #pragma unroll
            for (int j = 0; j < 4; j++)
                acc[i][j] += av[i] * bv[j];
    }
    #pragma unroll
    for (int i = 0; i < 4; i++) {
        float na = sna[r0+i];
        #pragma unroll
        for (int j = 0; j < 4; j++) {
            int c = c0 + 16*j;
            g_cos[(size_t)(i0 + r0 + i)*NN + j0 + c] = acc[i][j] / (na * snb[c]);
        }
    }
}

// ============================================================
// kernel 1b: top-20 selection, warp per row, 32 blocks x 16 warps.
// ============================================================
__global__ void k_sel(int dummy) {
    int tid = threadIdx.x;                 // 512
    int w = tid >> 5, lane = tid & 31;
    int n = blockIdx.x * 16 + w;

    float sl[16];
    #pragma unroll
    for (int j = 0; j < 16; j++) sl[j] = g_cos[(size_t)n*NN + j*32 + lane];

    for (int k = 0; k < TOPK; k++) {
        float bv = sl[0]; int bi = lane;
        #pragma unroll
        for (int j = 1; j < 16; j++) {
            int idx = j*32 + lane;
            if (sl[j] > bv) { bv = sl[j]; bi = idx; }
        }
        #pragma unroll
        for (int o = 16; o > 0; o >>= 1) {
            float ov = __shfl_xor_sync(0xFFFFFFFFu, bv, o);
            int   oi = __shfl_xor_sync(0xFFFFFFFFu, bi, o);
            if (ov > bv || (ov == bv && oi < bi)) { bv = ov; bi = oi; }
        }
        if (lane == 0) g_topk[n*TOPK + k] = bi;
        if ((bi & 31) == lane) {
            int j = bi >> 5;
            #pragma unroll
            for (int jj = 0; jj < 16; jj++) if (jj == j) sl[jj] = -INFINITY;
        }
    }
    (void)dummy;
}

// ============================================================
// kernel 2 (mega): per-batch block, 1024 threads.
//  phase 1: load data[b] -> zs (XOR-swizzled), fc_w -> hi/lo smem
//  phase 2: in-block split-tf32 MMA: z[b] = data[b]@fc_w^T + b
//           (warp w owns rows w*16..w*16+15; scores fused)
//  phase 3: edge softmax (alphas)
//  phase 4: gather/aggregate + BN partials (rst -> g_rst)
//  phase 5: software grid-sync, BN stats, normalize+relu+out.
// dyn smem: zs[512*64] | rg2[20480 floats]  (213 KB)
//   rg2 holds: B hi/lo during MMA -> apack during gather -> wsum/wsq
// swizzle: element d of row r stored at  d ^ ((r&7)*4).
// ============================================================
__global__ void __launch_bounds__(1024, 1)
k_aggr(const float* __restrict__ data, const float* __restrict__ fc_w,
       const float* __restrict__ fc_b, const float* __restrict__ attn_w,
       const float* __restrict__ emb, const float* __restrict__ attn_b,
       const float* __restrict__ bn_gamma, const float* __restrict__ bn_beta,
       const float* __restrict__ out_w, const float* __restrict__ out_b,
       float* __restrict__ out) {
    extern __shared__ float smem[];
    float*  zs  = smem;                               // 32768 floats
    float*  rg2 = smem + NN*DD;                       // 20480 floats
    float*  sBh = rg2;                                // 64*68 = 4352
    float*  sBl = rg2 + 64*BP;                        // 4352
    float2* apack = (float2*)rg2;                     // 10240 float2 (phase 3+)
    float*  wsum = rg2;                               // [32][64]  (phase 4+)
    float*  wsq  = rg2 + 2048;                        // [32][64]
    __shared__ float s_ssrc[NN];
    __shared__ float s_sdst[NN];
    __shared__ unsigned int s_last;

    int tid = threadIdx.x;                            // 1024
    int b = blockIdx.x;
    int lane = tid & 31, w = tid >> 5;                // w: 0..31
    int g = lane >> 2, t = lane & 3;

    // ---- phase 1: load data[b] swizzled + split fc_w ----
    {
        const float4* dsrc = reinterpret_cast<const float4*>(data + (size_t)b * NN * DD);
        float4* zs4 = reinterpret_cast<float4*>(zs);
        #pragma unroll
        for (int i = 0; i < 8; i++) {
            int idx = tid + i*1024;                   // float4 index, 8192 total
            int row = idx >> 4, c4 = idx & 15;
            zs4[row*16 + (c4 ^ (row & 7))] = dsrc[idx];
        }
        #pragma unroll
        for (int i = 0; i < 4; i++) {
            int idx = tid + i*1024;                   // 4096 total
            int r = idx >> 6, c = idx & 63;
            float v = fc_w[idx];
            uint32_t hb = f2tf32(v);
            float hf = __uint_as_float(hb);
            sBh[r*BP + c] = hf;
            sBl[r*BP + c] = __uint_as_float(f2tf32(v - hf));
        }
    }
    __syncthreads();

    // ---- phase 2: in-block split-tf32 MMA, warp w -> rows w*16.. ----
    int r0 = w*16 + g;                                // and r0+8
    int sw = (r0 & 7) * 4;                            // (r0+8)&7 == r0&7
    {
        float acc[8][4] = {};
        #pragma unroll
        for (int kk = 0; kk < 8; kk++) {
            int c0a = kk*8 + t, c1a = c0a + 4;
            float a0f = zs[r0*64     + (c0a ^ sw)];
            float a1f = zs[(r0+8)*64 + (c0a ^ sw)];
            float a2f = zs[r0*64     + (c1a ^ sw)];
            float a3f = zs[(r0+8)*64 + (c1a ^ sw)];
            uint32_t ah0 = f2tf32(a0f), ah1 = f2tf32(a1f);
            uint32_t ah2 = f2tf32(a2f), ah3 = f2tf32(a3f);
            uint32_t al0 = f2tf32(a0f - __uint_as_float(ah0));
            uint32_t al1 = f2tf32(a1f - __uint_as_float(ah1));
            uint32_t al2 = f2tf32(a2f - __uint_as_float(ah2));
            uint32_t al3 = f2tf32(a3f - __uint_as_float(ah3));
            #pragma unroll
            for (int j = 0; j < 8; j++) {
                int bn = j*8 + g;
                uint32_t bh0 = __float_as_uint(sBh[bn*BP + c0a]);
                uint32_t bh1 = __float_as_uint(sBh[bn*BP + c1a]);
                uint32_t bl0 = __float_as_uint(sBl[bn*BP + c0a]);
                uint32_t bl1 = __float_as_uint(sBl[bn*BP + c1a]);
                MMA_TF32(acc[j], ah0, ah1, ah2, ah3, bh0, bh1);   // hi*hi
                MMA_TF32(acc[j], al0, al1, al2, al3, bh0, bh1);   // lo*hi
                MMA_TF32(acc[j], ah0, ah1, ah2, ah3, bl0, bl1);   // hi*lo
            }
        }

        // epilogue: bias, z -> zs (swizzled, own rows only), fused scores
        float ds0 = 0.f, dd0 = 0.f, ds1 = 0.f, dd1 = 0.f;
        #pragma unroll
        for (int j = 0; j < 8; j++) {
            int n0 = j*8 + 2*t;
            float b0 = __ldg(&fc_b[n0]), b1 = __ldg(&fc_b[n0+1]);
            float z00 = acc[j][0] + b0, z01 = acc[j][1] + b1;
            float z10 = acc[j][2] + b0, z11 = acc[j][3] + b1;
            float2 v0; v0.x = z00; v0.y = z01;
            float2 v1; v1.x = z10; v1.y = z11;
            *reinterpret_cast<float2*>(&zs[r0*64     + (n0 ^ sw)]) = v0;
            *reinterpret_cast<float2*>(&zs[(r0+8)*64 + (n0 ^ sw)]) = v1;
            float as0 = __ldg(&attn_w[n0]),     as1 = __ldg(&attn_w[n0+1]);
            float ad0 = __ldg(&attn_w[128+n0]), ad1 = __ldg(&attn_w[128+n0+1]);
            ds0 += z00*as0 + z01*as1;  dd0 += z00*ad0 + z01*ad1;
            ds1 += z10*as0 + z11*as1;  dd1 += z10*ad0 + z11*ad1;
        }
        #pragma unroll
        for (int o = 2; o > 0; o >>= 1) {
            ds0 += __shfl_down_sync(0xFFFFFFFFu, ds0, o, 4);
            dd0 += __shfl_down_sync(0xFFFFFFFFu, dd0, o, 4);
            ds1 += __shfl_down_sync(0xFFFFFFFFu, ds1, o, 4);
            dd1 += __shfl_down_sync(0xFFFFFFFFu, dd1, o, 4);
        }
        if (t == 0) {
            s_ssrc[r0]   = ds0 + g_tsrc[r0];
            s_sdst[r0]   = dd0 + g_tdst[r0];
            s_ssrc[r0+8] = ds1 + g_tsrc[r0+8];
            s_sdst[r0+8] = dd1 + g_tdst[r0+8];
        }
    }
    __syncthreads();    // z + scores complete; B region free for apack

    // ---- phase 3: alphas (threads 0..511, one dst row each) ----
    if (tid < NN) {
        int n = tid;
        float sd = s_sdst[n] + __ldg(attn_b);
        float e[TOPK]; int sr[TOPK];
        float mx = -INFINITY;
        #pragma unroll
        for (int tt = 0; tt < TOPK; tt++) {
            int i = n + tt*NN;
            int s = g_topk[(i/TOPK)*TOPK + (i % TOPK)];   // reference's edge wiring
            sr[tt] = s;
            float x = s_ssrc[s] + sd;
            x = x > 0.f ? x : NEG_SLOPE * x;              // leaky relu
            e[tt] = x;
            mx = fmaxf(mx, x);
        }
        float den = 0.f;
        #pragma unroll
        for (int tt = 0; tt < TOPK; tt++) { float p = expf(e[tt] - mx); e[tt] = p; den += p; }
        float inv = 1.0f / den;
        #pragma unroll
        for (int tt = 0; tt < TOPK; tt++) {
            float2 pk; pk.x = e[tt]*inv; pk.y = __int_as_float(sr[tt]);
            apack[n*TOPK + tt] = pk;
        }
    }
    __syncthreads();

    // ---- phase 4: gather/aggregate; warp w -> rows w*16..w*16+15 ----
    float ps0 = 0.f, pq0 = 0.f, ps1 = 0.f, pq1 = 0.f;
    int nbase = w * 16;
    #pragma unroll
    for (int rr = 0; rr < 16; rr++) {
        int n = nbase + rr;
        float h0 = 0.f, h1 = 0.f;
        #pragma unroll
        for (int tt = 0; tt < TOPK; tt++) {
            float2 pk = apack[n*TOPK + tt];    // LDS.64 broadcast
            float a = pk.x;
            int   s = __float_as_int(pk.y);
            int idx0 = s*64 + (lane ^ ((s & 7) * 4));
            h0 = fmaf(a, zs[idx0],      h0);
            h1 = fmaf(a, zs[idx0 + 32], h1);
        }
        float e0 = emb[n*64 + lane];
        float e1 = emb[n*64 + 32 + lane];
        float v0 = h0 * e0, v1 = h1 * e1;
        size_t row = (size_t)b*NN + n;
        g_rst[row*64 + lane]      = v0;        // coalesced STG
        g_rst[row*64 + 32 + lane] = v1;
        ps0 += v0; pq0 += v0*v0;
        ps1 += v1; pq1 += v1*v1;
    }
    __syncthreads();                           // apack reads done -> reuse region
    wsum[w*64 + lane]    = ps0; wsum[w*64 + lane+32] = ps1;
    wsq [w*64 + lane]    = pq0; wsq [w*64 + lane+32] = pq1;
    __syncthreads();
    if (tid < 64) {
        float S = 0.f, Q = 0.f;
        #pragma unroll
        for (int ww = 0; ww < 32; ww++) { S += wsum[ww*64 + tid]; Q += wsq[ww*64 + tid]; }
        g_psum[b*64 + tid] = S;
        g_psq [b*64 + tid] = Q;
    }
    __threadfence();
    __syncthreads();
    if (tid == 0) s_last = (atomicAdd(&g_ctr, 1u) == BB - 1u) ? 1u : 0u;
    __syncthreads();

    if (s_last) {
        __threadfence();                       // acquire: all blocks' psum visible
        int d = tid & 63, grp = tid >> 6;      // 16 groups x 64 d, 8 batches each
        float s = 0.f, q = 0.f;
        #pragma unroll
        for (int jj = 0; jj < 8; jj++) {
            int j = grp*8 + jj;
            s += g_psum[j*64 + d];
            q += g_psq [j*64 + d];
        }
        __syncthreads();
        wsum[grp*64 + d] = s; wsq[grp*64 + d] = q;
        __syncthreads();
        if (tid < 64) {
            float S = 0.f, Q = 0.f;
            #pragma unroll
            for (int gg = 0; gg < 16; gg++) { S += wsum[gg*64 + tid]; Q += wsq[gg*64 + tid]; }
            float mu  = S / (float)M_ROWS;
            float var = Q / (float)M_ROWS - mu*mu;   // biased, matches jnp.var
            g_mu[tid]    = mu;
            g_scale[tid] = bn_gamma[tid] / sqrtf(var + BN_EPS);
        }
        __threadfence();
        __syncthreads();
        if (tid == 0) atomicExch(&g_done, 1u);
    }

    // grid-wide wait: 128 blocks, 1/SM, all co-resident
    if (tid == 0) {
        while (atomicAdd(&g_done, 0u) == 0u) { }
    }
    __syncthreads();
    __threadfence();

    // ---- phase 5: BN-normalize + relu + out projection ----
    {
        float mu0 = g_mu[lane],       mu1 = g_mu[lane+32];
        float sc0 = g_scale[lane],    sc1 = g_scale[lane+32];
        float bt0 = bn_beta[lane],    bt1 = bn_beta[lane+32];
        float ow0 = out_w[lane],      ow1 = out_w[lane+32];
        float ob  = __ldg(out_b);
        #pragma unroll
        for (int rr = 0; rr < 16; rr++) {
            size_t row = (size_t)b*NN + nbase + rr;
            float v0 = (g_rst[row*64 + lane]      - mu0) * sc0 + bt0;
            float v1 = (g_rst[row*64 + 32 + lane] - mu1) * sc1 + bt1;
            v0 = v0 > 0.f ? v0 : 0.f;
            v1 = v1 > 0.f ? v1 : 0.f;
            float a = v0*ow0 + v1*ow1;
            #pragma unroll
            for (int o = 16; o > 0; o >>= 1) a += __shfl_down_sync(0xFFFFFFFFu, a, o);
            if (lane == 0) out[b*NN + nbase + rr] = a + ob;
        }
    }

    // reset counters for next graph replay (last block to depart)
    __syncthreads();
    if (tid == 0) {
        if (atomicAdd(&g_ctr2, 1u) == BB - 1u) {
            g_ctr = 0; g_ctr2 = 0; g_done = 0;
            __threadfence();
        }
    }
}

extern "C" void kernel_launch(void* const* d_in, const int* in_sizes, int n_in,
                              void* d_out, int out_size) {
    const float* data     = (const float*)d_in[0];
    const float* emb      = (const float*)d_in[1];
    const float* fc_w     = (const float*)d_in[2];
    const float* fc_b     = (const float*)d_in[3];
    const float* attn_w   = (const float*)d_in[4];
    const float* attn_b   = (const float*)d_in[5];
    const float* bn_gamma = (const float*)d_in[6];
    const float* bn_beta  = (const float*)d_in[7];
    const float* out_w    = (const float*)d_in[8];
    const float* out_b    = (const float*)d_in[9];
    float* out = (float*)d_out;

    const int AGG_SMEM = (NN*DD + 2*NN*TOPK) * 4;    // 212992 bytes
    static int configured = 0;
    if (!configured) {
        cudaFuncSetAttribute(k_aggr, cudaFuncAttributeMaxDynamicSharedMemorySize, AGG_SMEM);
        configured = 1;
    }

    k_cos <<<dim3(8,8), 256>>>(emb, attn_w);
    k_sel <<<32, 512>>>(0);
    k_aggr<<<BB, 1024, AGG_SMEM>>>(data, fc_w, fc_b, attn_w,
                                   emb, attn_b, bn_gamma, bn_beta,
                                   out_w, out_b, out);
}

// round 14
// speedup vs baseline: 1.0987x; 1.0894x over previous
#include <cuda_runtime.h>
#include <math.h>
#include <stdint.h>

#define BB 128
#define NN 512
#define FT 64
#define DD 64
#define TOPK 20
#define M_ROWS (BB*NN)          // 65536
#define NEG_SLOPE 0.2f
#define BN_EPS 1e-5f
#define BP 68                   // B smem pitch (bank = 4g+t, conflict-free)

// ---- scratch (device globals; no allocation allowed) ----
__device__ int   g_topk[NN*TOPK];
__device__ float g_rst[M_ROWS*DD];      // 16 MB staging (coalesced)
__device__ float g_psum[BB*DD];
__device__ float g_psq[BB*DD];
__device__ float g_mu[DD];
__device__ float g_scale[DD];
__device__ unsigned int g_ctr_topk = 0;
__device__ unsigned int g_ctr  = 0;
__device__ unsigned int g_ctr2 = 0;
__device__ unsigned int g_done = 0;

__device__ __forceinline__ uint32_t f2tf32(float x) {
    uint32_t r;
    asm("cvt.rna.tf32.f32 %0, %1;" : "=r"(r) : "f"(x));
    return r;
}

#define MMA_TF32(ac, a0,a1,a2,a3, b0,b1) \
    asm volatile("mma.sync.aligned.m16n8k8.row.col.f32.tf32.tf32.f32 " \
        "{%0,%1,%2,%3}, {%4,%5,%6,%7}, {%8,%9}, {%0,%1,%2,%3};" \
        : "+f"((ac)[0]), "+f"((ac)[1]), "+f"((ac)[2]), "+f"((ac)[3]) \
        : "r"(a0), "r"(a1), "r"(a2), "r"(a3), "r"(b0), "r"(b1))

// ============================================================
// THE mega kernel: one launch, 128 blocks x 1024 threads.
//  phase 0: stage emb (rotation layout) -> zs; local norms,
//           tsrc/tdst; 4 cos rows per block; top-20 selection;
//           publish g_topk + arrive on topk counter.
//  phase 1: load data[b] -> zs (XOR swizzle), fc_w hi/lo split.
//  phase 2: in-block split-tf32 MMA z = data@fc_w^T + b; scores.
//  (wait for all blocks' topk)
//  phase 3: edge softmax (alphas).
//  phase 4: gather/aggregate + BN partials (rst -> g_rst).
//  phase 5: grid-sync, BN stats, normalize+relu+out-projection.
// dyn smem: zs[32768] | rg2[20480]  (213 KB)
//  rg2 overlays: cosv/norm/tsrc/tdst -> Bh/Bl(+tsrc/tdst) ->
//                apack -> wsum/wsq
// data swizzle: element d of row r at  d ^ ((r&7)*4).
// emb rotation: element d of row r at  (d + r) & 63.
// ============================================================
__global__ void __launch_bounds__(1024, 1)
k_mega(const float* __restrict__ data, const float* __restrict__ fc_w,
       const float* __restrict__ fc_b, const float* __restrict__ attn_w,
       const float* __restrict__ emb, const float* __restrict__ attn_b,
       const float* __restrict__ bn_gamma, const float* __restrict__ bn_beta,
       const float* __restrict__ out_w, const float* __restrict__ out_b,
       float* __restrict__ out) {
    extern __shared__ float smem[];
    float*  zs  = smem;                               // 32768 floats
    float*  rg2 = smem + NN*DD;                       // 20480 floats
    // phase-0 overlays
    float*  cosv  = rg2;                              // 2048 (4 x 512)
    float*  snorm = rg2 + 2048;                       // 512
    float*  s_ts  = rg2 + 8704;                       // 512 (lives into phase 2)
    float*  s_td  = rg2 + 9216;                       // 512
    // phase-1/2 overlays
    float*  sBh = rg2;                                // 64*68 = 4352
    float*  sBl = rg2 + 64*BP;                        // 4352 (ends 8704)
    // phase-3/4 overlays
    float2* apack = (float2*)rg2;                     // 10240 float2
    float*  wsum = rg2;                               // [32][64]
    float*  wsq  = rg2 + 2048;                        // [32][64]
    __shared__ float s_ssrc[NN];
    __shared__ float s_sdst[NN];
    __shared__ float s_aw[2*DD];                      // emb halves of a_src/a_dst
    __shared__ unsigned int s_last;

    int tid = threadIdx.x;                            // 1024
    int b = blockIdx.x;
    int lane = tid & 31, w = tid >> 5;                // w: 0..31
    int g = lane >> 2, t = lane & 3;

    // ---- phase 0a: stage emb (rotation layout) + attn_w emb-halves ----
    {
        const float4* esrc = reinterpret_cast<const float4*>(emb);
        #pragma unroll
        for (int i = 0; i < 8; i++) {
            int i4 = tid + i*1024;                    // 8192 float4 total
            float4 v = esrc[i4];
            int r = i4 >> 4;
            int c = (i4 & 15) * 4;
            zs[r*64 + ((c+0+r)&63)] = v.x;
            zs[r*64 + ((c+1+r)&63)] = v.y;
            zs[r*64 + ((c+2+r)&63)] = v.z;
            zs[r*64 + ((c+3+r)&63)] = v.w;
        }
        if (tid < 128) s_aw[tid] = attn_w[(tid < 64) ? (64 + tid) : (128 + tid)];
    }
    __syncthreads();

    // ---- phase 0b: norms (tid<512) and tsrc/tdst (tid>=512) ----
    if (tid < NN) {
        int r = tid;
        float s2 = 0.f;
        #pragma unroll 16
        for (int d = 0; d < 64; d++) { float v = zs[r*64 + ((d+r)&63)]; s2 += v*v; }
        snorm[r] = sqrtf(s2);
    } else {
        int r = tid - NN;
        float ts = 0.f, td = 0.f;
        #pragma unroll 16
        for (int d = 0; d < 64; d++) {
            float v = zs[r*64 + ((d+r)&63)];
            ts += v * s_aw[d];
            td += v * s_aw[64 + d];
        }
        s_ts[r] = ts;
        s_td[r] = td;
    }
    __syncthreads();

    // ---- phase 0c: 4 cos rows (n0..n0+3); thread: col m, 2 rows ----
    int n0 = b * 4;
    {
        int m  = tid & 511;
        int rl = tid >> 9;                            // 0 or 1
        int na = n0 + rl, nb = n0 + rl + 2;
        float d0 = 0.f, d1 = 0.f;
        #pragma unroll 8
        for (int d = 0; d < 64; d++) {
            float vm = zs[m*64 + ((d+m)&63)];         // conflict-free stream
            d0 += zs[na*64 + ((d+na)&63)] * vm;       // broadcast
            d1 += zs[nb*64 + ((d+nb)&63)] * vm;       // broadcast
        }
        float nm = snorm[m];
        cosv[rl*512 + m]     = d0 / (snorm[na] * nm);
        cosv[(rl+2)*512 + m] = d1 / (snorm[nb] * nm);
    }
    __syncthreads();

    // ---- phase 0d: top-20 selection, warps 0..3 -> rows n0..n0+3 ----
    if (w < 4) {
        float sl[16];
        #pragma unroll
        for (int j = 0; j < 16; j++) sl[j] = cosv[w*512 + j*32 + lane];
        for (int k = 0; k < TOPK; k++) {
            float bv = sl[0]; int bi = lane;
            #pragma unroll
            for (int j = 1; j < 16; j++) {
                int idx = j*32 + lane;
                if (sl[j] > bv) { bv = sl[j]; bi = idx; }
            }
            #pragma unroll
            for (int o = 16; o > 0; o >>= 1) {
                float ov = __shfl_xor_sync(0xFFFFFFFFu, bv, o);
                int   oi = __shfl_xor_sync(0xFFFFFFFFu, bi, o);
                if (ov > bv || (ov == bv && oi < bi)) { bv = ov; bi = oi; }
            }
            if (lane == 0) g_topk[(n0 + w)*TOPK + k] = bi;
            if ((bi & 31) == lane) {
                int j = bi >> 5;
                #pragma unroll
                for (int jj = 0; jj < 16; jj++) if (jj == j) sl[jj] = -INFINITY;
            }
        }
    }
    __threadfence();                                  // topk stores visible
    __syncthreads();
    if (tid == 0) atomicAdd(&g_ctr_topk, 1u);         // publish early

    // ---- phase 1: data[b] -> zs (XOR swizzle) + fc_w hi/lo split ----
    {
        const float4* dsrc = reinterpret_cast<const float4*>(data + (size_t)b * NN * DD);
        float4* zs4 = reinterpret_cast<float4*>(zs);
        #pragma unroll
        for (int i = 0; i < 8; i++) {
            int idx = tid + i*1024;
            int row = idx >> 4, c4 = idx & 15;
            zs4[row*16 + (c4 ^ (row & 7))] = dsrc[idx];
        }
        #pragma unroll
        for (int i = 0; i < 4; i++) {
            int idx = tid + i*1024;
            int r = idx >> 6, c = idx & 63;
            float v = fc_w[idx];
            uint32_t hb = f2tf32(v);
            float hf = __uint_as_float(hb);
            sBh[r*BP + c] = hf;
            sBl[r*BP + c] = __uint_as_float(f2tf32(v - hf));
        }
    }
    __syncthreads();

    // ---- phase 2: in-block split-tf32 MMA, warp w -> rows w*16.. ----
    int r0 = w*16 + g;                                // and r0+8
    int sw = (r0 & 7) * 4;
    {
        float acc[8][4] = {};
        #pragma unroll
        for (int kk = 0; kk < 8; kk++) {
            int c0a = kk*8 + t, c1a = c0a + 4;
            float a0f = zs[r0*64     + (c0a ^ sw)];
            float a1f = zs[(r0+8)*64 + (c0a ^ sw)];
            float a2f = zs[r0*64     + (c1a ^ sw)];
            float a3f = zs[(r0+8)*64 + (c1a ^ sw)];
            uint32_t ah0 = f2tf32(a0f), ah1 = f2tf32(a1f);
            uint32_t ah2 = f2tf32(a2f), ah3 = f2tf32(a3f);
            uint32_t al0 = f2tf32(a0f - __uint_as_float(ah0));
            uint32_t al1 = f2tf32(a1f - __uint_as_float(ah1));
            uint32_t al2 = f2tf32(a2f - __uint_as_float(ah2));
            uint32_t al3 = f2tf32(a3f - __uint_as_float(ah3));
            #pragma unroll
            for (int j = 0; j < 8; j++) {
                int bn = j*8 + g;
                uint32_t bh0 = __float_as_uint(sBh[bn*BP + c0a]);
                uint32_t bh1 = __float_as_uint(sBh[bn*BP + c1a]);
                uint32_t bl0 = __float_as_uint(sBl[bn*BP + c0a]);
                uint32_t bl1 = __float_as_uint(sBl[bn*BP + c1a]);
                MMA_TF32(acc[j], ah0, ah1, ah2, ah3, bh0, bh1);   // hi*hi
                MMA_TF32(acc[j], al0, al1, al2, al3, bh0, bh1);   // lo*hi
                MMA_TF32(acc[j], ah0, ah1, ah2, ah3, bl0, bl1);   // hi*lo
            }
        }

        // epilogue: bias, z -> zs (swizzled, own rows only), fused scores
        float ds0 = 0.f, dd0 = 0.f, ds1 = 0.f, dd1 = 0.f;
        #pragma unroll
        for (int j = 0; j < 8; j++) {
            int nn0 = j*8 + 2*t;
            float b0 = __ldg(&fc_b[nn0]), b1 = __ldg(&fc_b[nn0+1]);
            float z00 = acc[j][0] + b0, z01 = acc[j][1] + b1;
            float z10 = acc[j][2] + b0, z11 = acc[j][3] + b1;
            float2 v0; v0.x = z00; v0.y = z01;
            float2 v1; v1.x = z10; v1.y = z11;
            *reinterpret_cast<float2*>(&zs[r0*64     + (nn0 ^ sw)]) = v0;
            *reinterpret_cast<float2*>(&zs[(r0+8)*64 + (nn0 ^ sw)]) = v1;
            float as0 = __ldg(&attn_w[nn0]),     as1 = __ldg(&attn_w[nn0+1]);
            float ad0 = __ldg(&attn_w[128+nn0]), ad1 = __ldg(&attn_w[128+nn0+1]);
            ds0 += z00*as0 + z01*as1;  dd0 += z00*ad0 + z01*ad1;
            ds1 += z10*as0 + z11*as1;  dd1 += z10*ad0 + z11*ad1;
        }
        #pragma unroll
        for (int o = 2; o > 0; o >>= 1) {
            ds0 += __shfl_down_sync(0xFFFFFFFFu, ds0, o, 4);
            dd0 += __shfl_down_sync(0xFFFFFFFFu, dd0, o, 4);
            ds1 += __shfl_down_sync(0xFFFFFFFFu, ds1, o, 4);
            dd1 += __shfl_down_sync(0xFFFFFFFFu, dd1, o, 4);
        }
        if (t == 0) {
            s_ssrc[r0]   = ds0 + s_ts[r0];
            s_sdst[r0]   = dd0 + s_td[r0];
            s_ssrc[r0+8] = ds1 + s_ts[r0+8];
            s_sdst[r0+8] = dd1 + s_td[r0+8];
        }
    }
    __syncthreads();        // z + scores complete; rg2 free for apack

    // ---- wait: all blocks' topk published ----
    if (tid == 0) {
        while (atomicAdd(&g_ctr_topk, 0u) < BB) { }
    }
    __syncthreads();
    __threadfence();        // acquire g_topk

    // ---- phase 3: alphas (threads 0..511, one dst row each) ----
    if (tid < NN) {
        int n = tid;
        float sd = s_sdst[n] + __ldg(attn_b);
        float e[TOPK]; int sr[TOPK];
        float mx = -INFINITY;
        #pragma unroll
        for (int tt = 0; tt < TOPK; tt++) {
            int i = n + tt*NN;
            int s = g_topk[(i/TOPK)*TOPK + (i % TOPK)];   // reference's edge wiring
            sr[tt] = s;
            float x = s_ssrc[s] + sd;
            x = x > 0.f ? x : NEG_SLOPE * x;              // leaky relu
            e[tt] = x;
            mx = fmaxf(mx, x);
        }
        float den = 0.f;
        #pragma unroll
        for (int tt = 0; tt < TOPK; tt++) { float p = expf(e[tt] - mx); e[tt] = p; den += p; }
        float inv = 1.0f / den;
        #pragma unroll
        for (int tt = 0; tt < TOPK; tt++) {
            float2 pk; pk.x = e[tt]*inv; pk.y = __int_as_float(sr[tt]);
            apack[n*TOPK + tt] = pk;
        }
    }
    __syncthreads();

    // ---- phase 4: gather/aggregate; warp w -> rows w*16..w*16+15 ----
    float ps0 = 0.f, pq0 = 0.f, ps1 = 0.f, pq1 = 0.f;
    int nbase = w * 16;
    #pragma unroll
    for (int rr = 0; rr < 16; rr++) {
        int n = nbase + rr;
        float h0 = 0.f, h1 = 0.f;
        #pragma unroll
        for (int tt = 0; tt < TOPK; tt++) {
            float2 pk = apack[n*TOPK + tt];    // LDS.64 broadcast
            float a = pk.x;
            int   s = __float_as_int(pk.y);
            int idx0 = s*64 + (lane ^ ((s & 7) * 4));
            h0 = fmaf(a, zs[idx0],      h0);
            h1 = fmaf(a, zs[idx0 + 32], h1);
        }
        float e0 = emb[n*64 + lane];
        float e1 = emb[n*64 + 32 + lane];
        float v0 = h0 * e0, v1 = h1 * e1;
        size_t row = (size_t)b*NN + n;
        g_rst[row*64 + lane]      = v0;        // coalesced STG
        g_rst[row*64 + 32 + lane] = v1;
        ps0 += v0; pq0 += v0*v0;
        ps1 += v1; pq1 += v1*v1;
    }
    __syncthreads();                           // apack reads done -> reuse region
    wsum[w*64 + lane]    = ps0; wsum[w*64 + lane+32] = ps1;
    wsq [w*64 + lane]    = pq0; wsq [w*64 + lane+32] = pq1;
    __syncthreads();
    if (tid < 64) {
        float S = 0.f, Q = 0.f;
        #pragma unroll
        for (int ww = 0; ww < 32; ww++) { S += wsum[ww*64 + tid]; Q += wsq[ww*64 + tid]; }
        g_psum[b*64 + tid] = S;
        g_psq [b*64 + tid] = Q;
    }
    __threadfence();
    __syncthreads();
    if (tid == 0) s_last = (atomicAdd(&g_ctr, 1u) == BB - 1u) ? 1u : 0u;
    __syncthreads();

    if (s_last) {
        __threadfence();                       // acquire: all blocks' psum visible
        int d = tid & 63, grp = tid >> 6;      // 16 groups x 64 d, 8 batches each
        float s = 0.f, q = 0.f;
        #pragma unroll
        for (int jj = 0; jj < 8; jj++) {
            int j = grp*8 + jj;
            s += g_psum[j*64 + d];
            q += g_psq [j*64 + d];
        }
        __syncthreads();
        wsum[grp*64 + d] = s; wsq[grp*64 + d] = q;
        __syncthreads();
        if (tid < 64) {
            float S = 0.f, Q = 0.f;
            #pragma unroll
            for (int gg = 0; gg < 16; gg++) { S += wsum[gg*64 + tid]; Q += wsq[gg*64 + tid]; }
            float mu  = S / (float)M_ROWS;
            float var = Q / (float)M_ROWS - mu*mu;   // biased, matches jnp.var
            g_mu[tid]    = mu;
            g_scale[tid] = bn_gamma[tid] / sqrtf(var + BN_EPS);
        }
        __threadfence();
        __syncthreads();
        if (tid == 0) atomicExch(&g_done, 1u);
    }

    // grid-wide wait: 128 blocks, 1/SM, all co-resident
    if (tid == 0) {
        while (atomicAdd(&g_done, 0u) == 0u) { }
    }
    __syncthreads();
    __threadfence();

    // ---- phase 5: BN-normalize + relu + out projection ----
    {
        float mu0 = g_mu[lane],       mu1 = g_mu[lane+32];
        float sc0 = g_scale[lane],    sc1 = g_scale[lane+32];
        float bt0 = bn_beta[lane],    bt1 = bn_beta[lane+32];
        float ow0 = out_w[lane],      ow1 = out_w[lane+32];
        float ob  = __ldg(out_b);
        #pragma unroll
        for (int rr = 0; rr < 16; rr++) {
            size_t row = (size_t)b*NN + nbase + rr;
            float v0 = (g_rst[row*64 + lane]      - mu0) * sc0 + bt0;
            float v1 = (g_rst[row*64 + 32 + lane] - mu1) * sc1 + bt1;
            v0 = v0 > 0.f ? v0 : 0.f;
            v1 = v1 > 0.f ? v1 : 0.f;
            float a = v0*ow0 + v1*ow1;
            #pragma unroll
            for (int o = 16; o > 0; o >>= 1) a += __shfl_down_sync(0xFFFFFFFFu, a, o);
            if (lane == 0) out[b*NN + nbase + rr] = a + ob;
        }
    }

    // reset counters for next graph replay (last block to depart)
    __syncthreads();
    if (tid == 0) {
        if (atomicAdd(&g_ctr2, 1u) == BB - 1u) {
            g_ctr = 0; g_ctr2 = 0; g_done = 0; g_ctr_topk = 0;
            __threadfence();
        }
    }
}

extern "C" void kernel_launch(void* const* d_in, const int* in_sizes, int n_in,
                              void* d_out, int out_size) {
    const float* data     = (const float*)d_in[0];
    const float* emb      = (const float*)d_in[1];
    const float* fc_w     = (const float*)d_in[2];
    const float* fc_b     = (const float*)d_in[3];
    const float* attn_w   = (const float*)d_in[4];
    const float* attn_b   = (const float*)d_in[5];
    const float* bn_gamma = (const float*)d_in[6];
    const float* bn_beta  = (const float*)d_in[7];
    const float* out_w    = (const float*)d_in[8];
    const float* out_b    = (const float*)d_in[9];
    float* out = (float*)d_out;

    const int MEGA_SMEM = (NN*DD + 2*NN*TOPK) * 4;   // 212992 bytes
    static int configured = 0;
    if (!configured) {
        cudaFuncSetAttribute(k_mega, cudaFuncAttributeMaxDynamicSharedMemorySize, MEGA_SMEM);
        configured = 1;
    }

    k_mega<<<BB, 1024, MEGA_SMEM>>>(data, fc_w, fc_b, attn_w,
                                    emb, attn_b, bn_gamma, bn_beta,
                                    out_w, out_b, out);
}